// round 16
// baseline (speedup 1.0000x reference)
#include <cuda_runtime.h>
#include <cuda_fp16.h>
#include <stdint.h>
#include <math.h>

#define Bsz 16
#define Ssz 512
#define Tsz 128
#define Esz 256
#define VOUTsz 32000
#define ENCsz 32
#define DECsz 128

#define GM 2048            // B*T
#define GN 32000           // VOUT
#define GKH 128            // fp16 single-pass K

// ---------------- scratch (static device memory; no allocs) ----------------
__device__ __half g_srch[Bsz*Ssz*Esz];          // embedded source fp16  4 MB
__device__ float g_Xc[Bsz*Ssz*4*2*ENCsz];       // fused fwd|bwd gates   8 MB
__device__ __half g_Wcath[Esz*256];             // [Wf|Wb] fp16        128 KB
__device__ float g_bcat[256];
__device__ __half g_Wdh[320*512];               // Wd fp16             320 KB
__device__ float g_enc[Bsz*Ssz*2*ENCsz];        // encoder outputs       2 MB
__device__ float g_hidden[Bsz*2*ENCsz];
__device__ float g_q[Bsz*DECsz];
__device__ float g_P[Bsz*Ssz*DECsz];            // enc @ W2 + b2         4 MB
__device__ float g_scores[Bsz*Ssz];
__device__ float g_ctx[Bsz*2*ENCsz];
__device__ __half g_Xh[Bsz*Tsz*(2*ENCsz+Esz)];  // [ctx, temb] fp16    1.3 MB
__device__ float g_Z[Bsz*Tsz*4*DECsz];          // decoder gate pre-act  4 MB
__device__ __half g_Ah[GM*GKH];                 // decoder hidden fp16 512 KB
__device__ __half g_Bh[GKH*GN];                 // Wfc fp16              8 MB

// ---------------- math helpers ---------------------------------------------
__device__ __forceinline__ float sigf(float x) {
    return 1.0f / (1.0f + __expf(-x));
}
__device__ __forceinline__ float tanhfast(float x) {
    float ax = fabsf(x);
    float t = __expf(-2.0f * ax);
    float r = (1.0f - t) / (1.0f + t);
    return (x >= 0.0f) ? r : -r;
}

// ---------------- K-embed: embedding + positional encoding (fp32/MUFU) -----
__global__ void k_embed(const int* __restrict__ src_tok,
                        const float* __restrict__ emb) {
    int bs = blockIdx.x;
    int e  = threadIdx.x;
    int s  = bs & (Ssz - 1);
    int tok = src_tok[bs];
    int j = (e < Esz/2) ? e : (e - Esz/2);
    float rate = exp2f((float)j * (-0.103810253f));   // log2(1e4)/128
    float ang = (float)s * rate;
    float k = rintf(ang * 0.15915494309f);
    float r = fmaf(-k, 6.28318548f, ang);
    r = fmaf(k, 1.7484556e-7f, r);
    float pe = (e < Esz/2) ? __sinf(r) : __cosf(r);
    g_srch[bs*Esz + e] = __float2half(emb[tok*Esz + e] * 16.0f + pe);
}

// ---------------- converters -------------------------------------------------
__global__ void k_convB16(const float* __restrict__ Wfc) {
    int k = blockIdx.y;
    int n = blockIdx.x * 256 + threadIdx.x;
    g_Bh[k * GN + n] = __float2half(Wfc[k * GN + n]);
}
__global__ void k_convWd(const float* __restrict__ Wd) {
    int idx = blockIdx.x * 256 + threadIdx.x;   // 320*512 = 163840
    g_Wdh[idx] = __float2half(Wd[idx]);
}
__global__ void k_cat(const float* __restrict__ Wf, const float* __restrict__ bfv,
                      const float* __restrict__ Wb, const float* __restrict__ bbv) {
    int k = blockIdx.x, n = threadIdx.x;
    float w = (n < 128) ? Wf[k * 128 + n] : Wb[k * 128 + n - 128];
    g_Wcath[k * 256 + n] = __float2half(w);
    if (k == 0) g_bcat[n] = (n < 128) ? bfv[n] : bbv[n - 128];
}

// ---------------- generic fp32 GEMM (f32x2) — kept only for attention P ----
__global__ __launch_bounds__(256) void k_sgemm_bias(
    const float* __restrict__ A, const float* __restrict__ Bm,
    const float* __restrict__ bias, float* __restrict__ C,
    int M, int N, int K)
{
    __shared__ float As[16][128];
    __shared__ float Bs[16][128];
    const int n0 = blockIdx.x * 128;
    const int m0 = blockIdx.y * 128;
    const int tid = threadIdx.x;
    const int tx = tid & 15;
    const int ty = tid >> 4;

    unsigned long long acc[8][4];
#pragma unroll
    for (int r = 0; r < 8; r++)
#pragma unroll
        for (int c = 0; c < 4; c++) acc[r][c] = 0ULL;

    const int ar = tid >> 2;
    const int ac = (tid & 3) * 4;
    const int br = tid >> 5;
    const int bc = (tid & 31) * 4;

    for (int k0 = 0; k0 < K; k0 += 16) {
        float4 a0 = *(const float4*)&A[(m0 + ar) * K + k0 + ac];
        float4 a1 = *(const float4*)&A[(m0 + ar + 64) * K + k0 + ac];
        float4 b0 = *(const float4*)&Bm[(k0 + br) * N + n0 + bc];
        float4 b1 = *(const float4*)&Bm[(k0 + br + 8) * N + n0 + bc];
        As[ac+0][ar] = a0.x;  As[ac+1][ar] = a0.y;
        As[ac+2][ar] = a0.z;  As[ac+3][ar] = a0.w;
        As[ac+0][ar+64] = a1.x;  As[ac+1][ar+64] = a1.y;
        As[ac+2][ar+64] = a1.z;  As[ac+3][ar+64] = a1.w;
        *(float4*)&Bs[br][bc]     = b0;
        *(float4*)&Bs[br + 8][bc] = b1;
        __syncthreads();
#pragma unroll
        for (int k = 0; k < 16; k++) {
            float4 af0 = *(const float4*)&As[k][ty * 8];
            float4 af1 = *(const float4*)&As[k][ty * 8 + 4];
            ulonglong2 bb0 = *(const ulonglong2*)&Bs[k][tx * 8];
            ulonglong2 bb1 = *(const ulonglong2*)&Bs[k][tx * 8 + 4];
            unsigned long long bp0 = bb0.x, bp1 = bb0.y, bp2 = bb1.x, bp3 = bb1.y;
            float av[8] = {af0.x, af0.y, af0.z, af0.w, af1.x, af1.y, af1.z, af1.w};
#pragma unroll
            for (int r = 0; r < 8; r++) {
                unsigned long long ap;
                asm("mov.b64 %0, {%1, %1};" : "=l"(ap) : "f"(av[r]));
                asm("fma.rn.f32x2 %0, %1, %2, %0;" : "+l"(acc[r][0]) : "l"(ap), "l"(bp0));
                asm("fma.rn.f32x2 %0, %1, %2, %0;" : "+l"(acc[r][1]) : "l"(ap), "l"(bp1));
                asm("fma.rn.f32x2 %0, %1, %2, %0;" : "+l"(acc[r][2]) : "l"(ap), "l"(bp2));
                asm("fma.rn.f32x2 %0, %1, %2, %0;" : "+l"(acc[r][3]) : "l"(ap), "l"(bp3));
            }
        }
        __syncthreads();
    }
    float bsv[8];
#pragma unroll
    for (int i = 0; i < 8; i++) bsv[i] = bias[n0 + tx * 8 + i];
#pragma unroll
    for (int r = 0; r < 8; r++) {
        int row = m0 + ty * 8 + r;
        float out[8];
#pragma unroll
        for (int c = 0; c < 4; c++) {
            float lo, hi;
            asm("mov.b64 {%0, %1}, %2;" : "=f"(lo), "=f"(hi) : "l"(acc[r][c]));
            out[2*c]   = lo + bsv[2*c];
            out[2*c+1] = hi + bsv[2*c+1];
        }
        *(float4*)&C[row * N + n0 + tx * 8]     = make_float4(out[0], out[1], out[2], out[3]);
        *(float4*)&C[row * N + n0 + tx * 8 + 4] = make_float4(out[4], out[5], out[6], out[7]);
    }
}

// ---------------- generic fp16 GEMM: C = A@B + bias, fp32 accum -------------
#define HLDA 72
#define HLDB 136
#define HSA (128 * HLDA)
#define HSB (64 * HLDB)
#define HSTG (HSA + HSB)
#define SMEM_HG (2 * HSTG * 2)

__device__ __forceinline__ void hg_load_stage(
    const __half* A, const __half* Bm, __half* sm, int stage,
    int m0, int n0, int kt, int K, int N, int tid)
{
    __half* sA = sm + stage * HSTG;
    __half* sB = sA + HSA;
#pragma unroll
    for (int i = 0; i < 4; i++) {
        int ch = tid + i * 256;
        int row = ch >> 3, c8 = ch & 7;
        uint32_t dst;
        asm("{ .reg .u64 t; cvta.to.shared.u64 t, %1; cvt.u32.u64 %0, t; }"
            : "=r"(dst) : "l"(sA + row * HLDA + c8 * 8));
        asm volatile("cp.async.cg.shared.global [%0], [%1], 16;"
                     :: "r"(dst), "l"(&A[(m0 + row) * K + kt * 64 + c8 * 8]));
    }
#pragma unroll
    for (int i = 0; i < 4; i++) {
        int ch = tid + i * 256;
        int row = ch >> 4, c8 = ch & 15;
        uint32_t dst;
        asm("{ .reg .u64 t; cvta.to.shared.u64 t, %1; cvt.u32.u64 %0, t; }"
            : "=r"(dst) : "l"(sB + row * HLDB + c8 * 8));
        asm volatile("cp.async.cg.shared.global [%0], [%1], 16;"
                     :: "r"(dst), "l"(&Bm[(kt * 64 + row) * N + n0 + c8 * 8]));
    }
    asm volatile("cp.async.commit_group;" ::: "memory");
}

__global__ __launch_bounds__(256) void k_hgemm_bias(
    const __half* __restrict__ A, const __half* __restrict__ Bm,
    const float* __restrict__ bias, float* __restrict__ C,
    int M, int N, int K)
{
    extern __shared__ __half smh[];
    const int tid = threadIdx.x;
    const int warp = tid >> 5;
    const int lane = tid & 31;
    const int wm = warp >> 1;
    const int wn = warp & 1;
    const int n0 = blockIdx.x * 128;
    const int m0 = blockIdx.y * 128;
    const int KT = K >> 6;

    float acc[2][8][4];
#pragma unroll
    for (int i = 0; i < 2; i++)
#pragma unroll
        for (int j = 0; j < 8; j++)
#pragma unroll
            for (int k = 0; k < 4; k++) acc[i][j][k] = 0.0f;

    hg_load_stage(A, Bm, smh, 0, m0, n0, 0, K, N, tid);

    const int a_row = wm * 32 + (lane & 15);
    const int a_col = (lane >> 4) * 8;
    const int b_row = (lane & 15);
    const int b_col = wn * 64 + (lane >> 4) * 8;

    for (int kt = 0; kt < KT; kt++) {
        if (kt + 1 < KT) {
            hg_load_stage(A, Bm, smh, (kt + 1) & 1, m0, n0, kt + 1, K, N, tid);
            asm volatile("cp.async.wait_group 1;" ::: "memory");
        } else {
            asm volatile("cp.async.wait_group 0;" ::: "memory");
        }
        __syncthreads();
        __half* sA = smh + (kt & 1) * HSTG;
        __half* sB = sA + HSA;
#pragma unroll
        for (int kk = 0; kk < 4; kk++) {
            unsigned af[2][4];
#pragma unroll
            for (int mt = 0; mt < 2; mt++) {
                unsigned saddr = (unsigned)__cvta_generic_to_shared(
                    &sA[(a_row + mt * 16) * HLDA + a_col + kk * 16]);
                asm volatile(
                    "ldmatrix.sync.aligned.m8n8.x4.shared.b16 {%0,%1,%2,%3}, [%4];"
                    : "=r"(af[mt][0]), "=r"(af[mt][1]), "=r"(af[mt][2]), "=r"(af[mt][3])
                    : "r"(saddr));
            }
            unsigned bfr[8][2];
#pragma unroll
            for (int nb = 0; nb < 4; nb++) {
                unsigned saddr = (unsigned)__cvta_generic_to_shared(
                    &sB[(b_row + kk * 16) * HLDB + b_col + nb * 16]);
                unsigned r0, r1, r2, r3;
                asm volatile(
                    "ldmatrix.sync.aligned.m8n8.x4.trans.shared.b16 {%0,%1,%2,%3}, [%4];"
                    : "=r"(r0), "=r"(r1), "=r"(r2), "=r"(r3)
                    : "r"(saddr));
                bfr[nb * 2][0] = r0;     bfr[nb * 2][1] = r1;
                bfr[nb * 2 + 1][0] = r2; bfr[nb * 2 + 1][1] = r3;
            }
#pragma unroll
            for (int mt = 0; mt < 2; mt++)
#pragma unroll
                for (int nt = 0; nt < 8; nt++) {
                    asm volatile(
                        "mma.sync.aligned.m16n8k16.row.col.f32.f16.f16.f32 "
                        "{%0,%1,%2,%3},{%4,%5,%6,%7},{%8,%9},{%0,%1,%2,%3};"
                        : "+f"(acc[mt][nt][0]), "+f"(acc[mt][nt][1]),
                          "+f"(acc[mt][nt][2]), "+f"(acc[mt][nt][3])
                        : "r"(af[mt][0]), "r"(af[mt][1]), "r"(af[mt][2]), "r"(af[mt][3]),
                          "r"(bfr[nt][0]), "r"(bfr[nt][1]));
                }
        }
        __syncthreads();
    }

#pragma unroll
    for (int mt = 0; mt < 2; mt++) {
        int row = m0 + wm * 32 + mt * 16 + (lane >> 2);
#pragma unroll
        for (int nt = 0; nt < 8; nt++) {
            int col = n0 + wn * 64 + nt * 8 + 2 * (lane & 3);
            float2 bb = *(const float2*)&bias[col];
            float2 v0 = make_float2(acc[mt][nt][0] + bb.x, acc[mt][nt][1] + bb.y);
            float2 v1 = make_float2(acc[mt][nt][2] + bb.x, acc[mt][nt][3] + bb.y);
            *(float2*)&C[row * N + col]       = v0;
            *(float2*)&C[(row + 8) * N + col] = v1;
        }
    }
}

// ---------------- K3: LSTM recurrence v3b — smem h-broadcast + f32x2 -------
// One warp per (batch, dir). Lane j owns h[j], c[j] and 4 gate columns packed
// as f32x2 pairs (i,f) and (g,o). FIX vs v3: pack the CURRENT step's x gates
// BEFORE the next-step prefetch overwrites xi/xf/xg/xo.
__global__ __launch_bounds__(32) void k_lstm_warp(const float* __restrict__ Uf,
                                                  const float* __restrict__ Ub) {
    __shared__ __align__(16) float shh[128];   // 2 buffers x 64 floats
    int blk = blockIdx.x;
    int batch = blk >> 1;
    int dir = blk & 1;
    const float* U = dir ? Ub : Uf;
    int j = threadIdx.x;

    unsigned long long uIF[32], uGO[32];  // packed (Ui,Uf), (Ug,Uo) columns
#pragma unroll
    for (int k = 0; k < 32; k++) {
        float a = U[k * 128 + j];
        float b = U[k * 128 + 32 + j];
        float g = U[k * 128 + 64 + j];
        float o = U[k * 128 + 96 + j];
        asm("mov.b64 %0, {%1, %2};" : "=l"(uIF[k]) : "f"(a), "f"(b));
        asm("mov.b64 %0, {%1, %2};" : "=l"(uGO[k]) : "f"(g), "f"(o));
    }

    float h = 0.0f, c = 0.0f;
    int s = dir ? (Ssz - 1) : 0;
    int step = dir ? -1 : 1;
    const float* Xbase = g_Xc + batch * Ssz * 256 + dir * 128;
    const float* p0 = Xbase + s * 256;
    float xi = p0[j], xf = p0[32 + j], xg = p0[64 + j], xo = p0[96 + j];

    for (int t = 0; t < Ssz; t++) {
        float* buf = shh + (t & 1) * 64;
        buf[2 * j]     = h;
        buf[2 * j + 1] = h;
        __syncwarp();

        // pack CURRENT x gates first (before prefetch clobbers them)
        unsigned long long aIF[4], aGO[4];
        asm("mov.b64 %0, {%1, %2};" : "=l"(aIF[0]) : "f"(xi), "f"(xf));
        asm("mov.b64 %0, {%1, %2};" : "=l"(aGO[0]) : "f"(xg), "f"(xo));
        aIF[1] = aIF[2] = aIF[3] = 0ULL;
        aGO[1] = aGO[2] = aGO[3] = 0ULL;

        int s_cur = s;
        s += step;
        if (t + 1 < Ssz) {                       // prefetch next step's x@W
            const float* p = Xbase + s * 256;
            xi = p[j]; xf = p[32 + j]; xg = p[64 + j]; xo = p[96 + j];
        }

#pragma unroll
        for (int m = 0; m < 16; m++) {
            ulonglong2 hv = *(const ulonglong2*)&buf[4 * m];  // (h2m,h2m),(h2m+1,h2m+1)
            int s0 = (m & 1) * 2;
            asm("fma.rn.f32x2 %0, %1, %2, %0;" : "+l"(aIF[s0])     : "l"(hv.x), "l"(uIF[2*m]));
            asm("fma.rn.f32x2 %0, %1, %2, %0;" : "+l"(aIF[s0 + 1]) : "l"(hv.y), "l"(uIF[2*m+1]));
            asm("fma.rn.f32x2 %0, %1, %2, %0;" : "+l"(aGO[s0])     : "l"(hv.x), "l"(uGO[2*m]));
            asm("fma.rn.f32x2 %0, %1, %2, %0;" : "+l"(aGO[s0 + 1]) : "l"(hv.y), "l"(uGO[2*m+1]));
        }
        asm("add.rn.f32x2 %0, %0, %1;" : "+l"(aIF[0]) : "l"(aIF[2]));
        asm("add.rn.f32x2 %0, %0, %1;" : "+l"(aIF[1]) : "l"(aIF[3]));
        asm("add.rn.f32x2 %0, %0, %1;" : "+l"(aIF[0]) : "l"(aIF[1]));
        asm("add.rn.f32x2 %0, %0, %1;" : "+l"(aGO[0]) : "l"(aGO[2]));
        asm("add.rn.f32x2 %0, %0, %1;" : "+l"(aGO[1]) : "l"(aGO[3]));
        asm("add.rn.f32x2 %0, %0, %1;" : "+l"(aGO[0]) : "l"(aGO[1]));
        float zi, zf, zg, zo;
        asm("mov.b64 {%0, %1}, %2;" : "=f"(zi), "=f"(zf) : "l"(aIF[0]));
        asm("mov.b64 {%0, %1}, %2;" : "=f"(zg), "=f"(zo) : "l"(aGO[0]));

        c = sigf(zf) * c + sigf(zi) * tanhfast(zg);
        h = sigf(zo) * tanhfast(c);
        g_enc[(batch * Ssz + s_cur) * 64 + dir * 32 + j] = h;
    }
    g_hidden[batch * 64 + dir * 32 + j] = h;
}

// ---------------- K4: attention --------------------------------------------
__global__ void k_q(const float* __restrict__ W1, const float* __restrict__ b1) {
    __shared__ float hh[64];
    int b = blockIdx.x, t = threadIdx.x;
    if (t < 64) hh[t] = g_hidden[b * 64 + t];
    __syncthreads();
    float acc = b1[t];
#pragma unroll
    for (int k = 0; k < 64; k++) acc += hh[k] * W1[k * 128 + t];
    g_q[b * 128 + t] = acc;
}

__global__ void k_score(const float* __restrict__ Vw, const float* __restrict__ Vb) {
    int warp = threadIdx.x >> 5;
    int lane = threadIdx.x & 31;
    int row = blockIdx.x * 8 + warp;
    int b = row >> 9;
    const float* Prow = g_P + row * 128;
    const float* qrow = g_q + b * 128;
    float sum = 0.0f;
#pragma unroll
    for (int i = 0; i < 4; i++) {
        int d = i * 32 + lane;
        sum += tanhfast(Prow[d] + qrow[d]) * Vw[d];
    }
#pragma unroll
    for (int o = 16; o > 0; o >>= 1) sum += __shfl_xor_sync(0xffffffffu, sum, o);
    if (lane == 0) g_scores[row] = sum + Vb[0];
}

__global__ __launch_bounds__(256) void k_attn() {
    __shared__ float sw[512];
    __shared__ float sbuf[256];
    int b = blockIdx.x, tid = threadIdx.x;
    float s0 = g_scores[b * 512 + tid];
    float s1 = g_scores[b * 512 + 256 + tid];
    sbuf[tid] = fmaxf(s0, s1);
    __syncthreads();
    for (int o = 128; o > 0; o >>= 1) {
        if (tid < o) sbuf[tid] = fmaxf(sbuf[tid], sbuf[tid + o]);
        __syncthreads();
    }
    float mx = sbuf[0];
    __syncthreads();
    float w0 = __expf(s0 - mx), w1 = __expf(s1 - mx);
    sw[tid] = w0; sw[tid + 256] = w1;
    sbuf[tid] = w0 + w1;
    __syncthreads();
    for (int o = 128; o > 0; o >>= 1) {
        if (tid < o) sbuf[tid] += sbuf[tid + o];
        __syncthreads();
    }
    float inv = 1.0f / sbuf[0];
    __syncthreads();
    int k = tid & 63, chunk = tid >> 6;
    float partial = 0.0f;
    for (int s = chunk * 128; s < chunk * 128 + 128; s++)
        partial += sw[s] * g_enc[(b * 512 + s) * 64 + k];
    sbuf[tid] = partial;
    __syncthreads();
    if (tid < 64)
        g_ctx[b * 64 + tid] =
            (sbuf[tid] + sbuf[tid + 64] + sbuf[tid + 128] + sbuf[tid + 192]) * inv;
}

// ---------------- K5: decoder ------------------------------------------------
__global__ void k_buildx(const int* __restrict__ tgt, const float* __restrict__ temb) {
    int row = blockIdx.x;
    int t = threadIdx.x;
    float v;
    if (t < 64) v = g_ctx[(row >> 7) * 64 + t];
    else        v = temb[tgt[row] * 256 + (t - 64)];
    g_Xh[row * 320 + t] = __float2half(v);
}

__global__ void k_gateA() {
    int idx = blockIdx.x * 256 + threadIdx.x;
    int row = idx >> 7, j = idx & 127;
    const float* z = g_Z + row * 512;
    float c = sigf(z[j]) * tanhfast(z[256 + j]);        // i, g (f is dead)
    float h = sigf(z[384 + j]) * tanhfast(c);           // o
    g_Ah[idx] = __float2half(h);
}

// ---------------- K6: vocab projection, fp16 mma.sync (one-shot K=128) ------
#define LDT 136
#define SMEM_VOC (2 * 128 * LDT * 2)   // sA + sB fp16

__global__ __launch_bounds__(256, 2) void k_vocab_f16(const float* __restrict__ bias,
                                                      float* __restrict__ C) {
    extern __shared__ __half smh[];
    __half* sA = smh;                  // 128 x LDT
    __half* sB = smh + 128 * LDT;      // 128 x LDT
    const int tid = threadIdx.x;
    const int warp = tid >> 5;
    const int lane = tid & 31;
    const int wm = warp >> 1;
    const int wn = warp & 1;
    const int n0 = blockIdx.x * 128;
    const int m0 = blockIdx.y * 128;

#pragma unroll
    for (int i = 0; i < 8; i++) {
        int ch = tid + i * 256;
        int row = ch >> 4, c8 = ch & 15;
        uint32_t dst;
        asm("{ .reg .u64 t; cvta.to.shared.u64 t, %1; cvt.u32.u64 %0, t; }"
            : "=r"(dst) : "l"(sA + row * LDT + c8 * 8));
        asm volatile("cp.async.cg.shared.global [%0], [%1], 16;"
                     :: "r"(dst), "l"(&g_Ah[(m0 + row) * GKH + c8 * 8]));
    }
#pragma unroll
    for (int i = 0; i < 8; i++) {
        int ch = tid + i * 256;
        int row = ch >> 4, c8 = ch & 15;
        uint32_t dst;
        asm("{ .reg .u64 t; cvta.to.shared.u64 t, %1; cvt.u32.u64 %0, t; }"
            : "=r"(dst) : "l"(sB + row * LDT + c8 * 8));
        asm volatile("cp.async.cg.shared.global [%0], [%1], 16;"
                     :: "r"(dst), "l"(&g_Bh[row * GN + n0 + c8 * 8]));
    }
    asm volatile("cp.async.commit_group;" ::: "memory");
    asm volatile("cp.async.wait_group 0;" ::: "memory");
    __syncthreads();

    float acc[2][8][4];
#pragma unroll
    for (int i = 0; i < 2; i++)
#pragma unroll
        for (int j = 0; j < 8; j++)
#pragma unroll
            for (int k = 0; k < 4; k++) acc[i][j][k] = 0.0f;

    const int a_row = wm * 32 + (lane & 15);
    const int a_col = (lane >> 4) * 8;
    const int b_row = (lane & 15);
    const int b_col = wn * 64 + (lane >> 4) * 8;

#pragma unroll
    for (int kk = 0; kk < 8; kk++) {
        unsigned af[2][4];
#pragma unroll
        for (int mt = 0; mt < 2; mt++) {
            unsigned saddr = (unsigned)__cvta_generic_to_shared(
                &sA[(a_row + mt * 16) * LDT + a_col + kk * 16]);
            asm volatile(
                "ldmatrix.sync.aligned.m8n8.x4.shared.b16 {%0,%1,%2,%3}, [%4];"
                : "=r"(af[mt][0]), "=r"(af[mt][1]), "=r"(af[mt][2]), "=r"(af[mt][3])
                : "r"(saddr));
        }
        unsigned bfr[8][2];
#pragma unroll
        for (int nb = 0; nb < 4; nb++) {
            unsigned saddr = (unsigned)__cvta_generic_to_shared(
                &sB[(b_row + kk * 16) * LDT + b_col + nb * 16]);
            unsigned r0, r1, r2, r3;
            asm volatile(
                "ldmatrix.sync.aligned.m8n8.x4.trans.shared.b16 {%0,%1,%2,%3}, [%4];"
                : "=r"(r0), "=r"(r1), "=r"(r2), "=r"(r3)
                : "r"(saddr));
            bfr[nb * 2][0] = r0;     bfr[nb * 2][1] = r1;
            bfr[nb * 2 + 1][0] = r2; bfr[nb * 2 + 1][1] = r3;
        }
#pragma unroll
        for (int mt = 0; mt < 2; mt++)
#pragma unroll
            for (int nt = 0; nt < 8; nt++) {
                asm volatile(
                    "mma.sync.aligned.m16n8k16.row.col.f32.f16.f16.f32 "
                    "{%0,%1,%2,%3},{%4,%5,%6,%7},{%8,%9},{%0,%1,%2,%3};"
                    : "+f"(acc[mt][nt][0]), "+f"(acc[mt][nt][1]),
                      "+f"(acc[mt][nt][2]), "+f"(acc[mt][nt][3])
                    : "r"(af[mt][0]), "r"(af[mt][1]), "r"(af[mt][2]), "r"(af[mt][3]),
                      "r"(bfr[nt][0]), "r"(bfr[nt][1]));
            }
    }

#pragma unroll
    for (int mt = 0; mt < 2; mt++) {
        int row = m0 + wm * 32 + mt * 16 + (lane >> 2);
#pragma unroll
        for (int nt = 0; nt < 8; nt++) {
            int col = n0 + wn * 64 + nt * 8 + 2 * (lane & 3);
            float2 bb = *(const float2*)&bias[col];
            float2 v0 = make_float2(acc[mt][nt][0] + bb.x, acc[mt][nt][1] + bb.y);
            float2 v1 = make_float2(acc[mt][nt][2] + bb.x, acc[mt][nt][3] + bb.y);
            *(float2*)&C[row * GN + col]       = v0;
            *(float2*)&C[(row + 8) * GN + col] = v1;
        }
    }
}

// ---------------- host launcher ---------------------------------------------
extern "C" void kernel_launch(void* const* d_in, const int* in_sizes, int n_in,
                              void* d_out, int out_size) {
    const int*   source  = (const int*)d_in[0];
    const int*   target  = (const int*)d_in[1];
    const float* src_emb = (const float*)d_in[2];
    const float* tgt_emb = (const float*)d_in[3];
    const float* Wf = (const float*)d_in[4];
    const float* Uf = (const float*)d_in[5];
    const float* bf = (const float*)d_in[6];
    const float* Wb = (const float*)d_in[7];
    const float* Ub = (const float*)d_in[8];
    const float* bb = (const float*)d_in[9];
    const float* W1 = (const float*)d_in[10];
    const float* b1 = (const float*)d_in[11];
    const float* W2 = (const float*)d_in[12];
    const float* b2 = (const float*)d_in[13];
    const float* Vw = (const float*)d_in[14];
    const float* Vb = (const float*)d_in[15];
    const float* Wd = (const float*)d_in[16];
    const float* bd = (const float*)d_in[17];
    const float* Wfc = (const float*)d_in[18];
    const float* bfc = (const float*)d_in[19];
    float* out = (float*)d_out;

    __half *p_srch, *p_Wcath, *p_Wdh, *p_Xh;
    float *p_Xc, *p_bcat, *p_enc, *p_P, *p_Z;
    cudaGetSymbolAddress((void**)&p_srch,  g_srch);
    cudaGetSymbolAddress((void**)&p_Wcath, g_Wcath);
    cudaGetSymbolAddress((void**)&p_Wdh,   g_Wdh);
    cudaGetSymbolAddress((void**)&p_Xh,    g_Xh);
    cudaGetSymbolAddress((void**)&p_Xc,    g_Xc);
    cudaGetSymbolAddress((void**)&p_bcat,  g_bcat);
    cudaGetSymbolAddress((void**)&p_enc,   g_enc);
    cudaGetSymbolAddress((void**)&p_P,     g_P);
    cudaGetSymbolAddress((void**)&p_Z,     g_Z);

    cudaFuncSetAttribute(k_vocab_f16,
                         cudaFuncAttributeMaxDynamicSharedMemorySize, SMEM_VOC);
    cudaFuncSetAttribute(k_hgemm_bias,
                         cudaFuncAttributeMaxDynamicSharedMemorySize, SMEM_HG);

    // critical path first (launch #4 = k_lstm_warp, for ncu's sampled slot)
    k_cat<<<256, 256>>>(Wf, bf, Wb, bb);
    k_embed<<<Bsz * Ssz, 256>>>(source, src_emb);
    k_hgemm_bias<<<dim3(2, 64), 256, SMEM_HG>>>(p_srch, p_Wcath, p_bcat, p_Xc, 8192, 256, 256);
    k_lstm_warp<<<32, 32>>>(Uf, Ub);
    // independent prep (off critical path)
    k_convB16<<<dim3(GN / 256, GKH), 256>>>(Wfc);
    k_convWd<<<640, 256>>>(Wd);
    // attention
    k_q<<<16, 128>>>(W1, b1);
    k_sgemm_bias<<<dim3(1, 64), 256>>>(p_enc, W2, b2, p_P, 8192, 128, 64);
    k_score<<<1024, 256>>>(Vw, Vb);
    k_attn<<<16, 256>>>();
    // decoder
    k_buildx<<<2048, 320>>>(target, tgt_emb);
    k_hgemm_bias<<<dim3(4, 16), 256, SMEM_HG>>>(p_Xh, p_Wdh, bd, p_Z, 2048, 512, 320);
    k_gateA<<<1024, 256>>>();
    // vocab projection
    k_vocab_f16<<<dim3(GN / 128, GM / 128), 256, SMEM_VOC>>>(bfc, out);
}

// round 17
// speedup vs baseline: 1.2392x; 1.2392x over previous
#include <cuda_runtime.h>
#include <cuda_fp16.h>
#include <stdint.h>
#include <math.h>

#define Bsz 16
#define Ssz 512
#define Tsz 128
#define Esz 256
#define VOUTsz 32000
#define ENCsz 32
#define DECsz 128

#define GM 2048            // B*T
#define GN 32000           // VOUT
#define GKH 128            // fp16 single-pass K

// ---------------- scratch (static device memory; no allocs) ----------------
__device__ __half g_srch[Bsz*Ssz*Esz];          // embedded source fp16  4 MB
__device__ float g_Xc[Bsz*Ssz*4*2*ENCsz];       // fused fwd|bwd gates   8 MB
__device__ __half g_Wcath[Esz*256];             // [Wf|Wb] fp16        128 KB
__device__ float g_bcat[256];
__device__ __half g_Wdh[320*512];               // Wd fp16             320 KB
__device__ float g_enc[Bsz*Ssz*2*ENCsz];        // encoder outputs       2 MB
__device__ float g_hidden[Bsz*2*ENCsz];
__device__ float g_q[Bsz*DECsz];
__device__ float g_P[Bsz*Ssz*DECsz];            // enc @ W2 + b2         4 MB
__device__ float g_scores[Bsz*Ssz];
__device__ float g_ctx[Bsz*2*ENCsz];
__device__ __half g_Xh[Bsz*Tsz*(2*ENCsz+Esz)];  // [ctx, temb] fp16    1.3 MB
__device__ float g_Z[Bsz*Tsz*4*DECsz];          // decoder gate pre-act  4 MB
__device__ __half g_Ah[GM*GKH];                 // decoder hidden fp16 512 KB
__device__ __half g_Bh[GKH*GN];                 // Wfc fp16              8 MB

// ---------------- math helpers ---------------------------------------------
// exact-ish versions (decoder/attention path — keeps output precision)
__device__ __forceinline__ float sigf(float x) {
    return 1.0f / (1.0f + __expf(-x));
}
__device__ __forceinline__ float tanhfast(float x) {
    float ax = fabsf(x);
    float t = __expf(-2.0f * ax);
    float r = (1.0f - t) / (1.0f + t);
    return (x >= 0.0f) ? r : -r;
}
// MUFU.TANH versions (encoder LSTM only; error washed out by softmax avg)
__device__ __forceinline__ float tanha(float x) {
    float y;
    asm("tanh.approx.f32 %0, %1;" : "=f"(y) : "f"(x));
    return y;
}
__device__ __forceinline__ float siga(float x) {
    return fmaf(tanha(0.5f * x), 0.5f, 0.5f);
}

// ---------------- K-embed: embedding + positional encoding (fp32/MUFU) -----
__global__ void k_embed(const int* __restrict__ src_tok,
                        const float* __restrict__ emb) {
    int bs = blockIdx.x;
    int e  = threadIdx.x;
    int s  = bs & (Ssz - 1);
    int tok = src_tok[bs];
    int j = (e < Esz/2) ? e : (e - Esz/2);
    float rate = exp2f((float)j * (-0.103810253f));   // log2(1e4)/128
    float ang = (float)s * rate;
    float k = rintf(ang * 0.15915494309f);
    float r = fmaf(-k, 6.28318548f, ang);
    r = fmaf(k, 1.7484556e-7f, r);
    float pe = (e < Esz/2) ? __sinf(r) : __cosf(r);
    g_srch[bs*Esz + e] = __float2half(emb[tok*Esz + e] * 16.0f + pe);
}

// ---------------- converters -------------------------------------------------
__global__ void k_convB16(const float* __restrict__ Wfc) {
    int k = blockIdx.y;
    int n = blockIdx.x * 256 + threadIdx.x;
    g_Bh[k * GN + n] = __float2half(Wfc[k * GN + n]);
}
__global__ void k_convWd(const float* __restrict__ Wd) {
    int idx = blockIdx.x * 256 + threadIdx.x;   // 320*512 = 163840
    g_Wdh[idx] = __float2half(Wd[idx]);
}
__global__ void k_cat(const float* __restrict__ Wf, const float* __restrict__ bfv,
                      const float* __restrict__ Wb, const float* __restrict__ bbv) {
    int k = blockIdx.x, n = threadIdx.x;
    float w = (n < 128) ? Wf[k * 128 + n] : Wb[k * 128 + n - 128];
    g_Wcath[k * 256 + n] = __float2half(w);
    if (k == 0) g_bcat[n] = (n < 128) ? bfv[n] : bbv[n - 128];
}

// ---------------- generic fp32 GEMM (f32x2) — kept only for attention P ----
__global__ __launch_bounds__(256) void k_sgemm_bias(
    const float* __restrict__ A, const float* __restrict__ Bm,
    const float* __restrict__ bias, float* __restrict__ C,
    int M, int N, int K)
{
    __shared__ float As[16][128];
    __shared__ float Bs[16][128];
    const int n0 = blockIdx.x * 128;
    const int m0 = blockIdx.y * 128;
    const int tid = threadIdx.x;
    const int tx = tid & 15;
    const int ty = tid >> 4;

    unsigned long long acc[8][4];
#pragma unroll
    for (int r = 0; r < 8; r++)
#pragma unroll
        for (int c = 0; c < 4; c++) acc[r][c] = 0ULL;

    const int ar = tid >> 2;
    const int ac = (tid & 3) * 4;
    const int br = tid >> 5;
    const int bc = (tid & 31) * 4;

    for (int k0 = 0; k0 < K; k0 += 16) {
        float4 a0 = *(const float4*)&A[(m0 + ar) * K + k0 + ac];
        float4 a1 = *(const float4*)&A[(m0 + ar + 64) * K + k0 + ac];
        float4 b0 = *(const float4*)&Bm[(k0 + br) * N + n0 + bc];
        float4 b1 = *(const float4*)&Bm[(k0 + br + 8) * N + n0 + bc];
        As[ac+0][ar] = a0.x;  As[ac+1][ar] = a0.y;
        As[ac+2][ar] = a0.z;  As[ac+3][ar] = a0.w;
        As[ac+0][ar+64] = a1.x;  As[ac+1][ar+64] = a1.y;
        As[ac+2][ar+64] = a1.z;  As[ac+3][ar+64] = a1.w;
        *(float4*)&Bs[br][bc]     = b0;
        *(float4*)&Bs[br + 8][bc] = b1;
        __syncthreads();
#pragma unroll
        for (int k = 0; k < 16; k++) {
            float4 af0 = *(const float4*)&As[k][ty * 8];
            float4 af1 = *(const float4*)&As[k][ty * 8 + 4];
            ulonglong2 bb0 = *(const ulonglong2*)&Bs[k][tx * 8];
            ulonglong2 bb1 = *(const ulonglong2*)&Bs[k][tx * 8 + 4];
            unsigned long long bp0 = bb0.x, bp1 = bb0.y, bp2 = bb1.x, bp3 = bb1.y;
            float av[8] = {af0.x, af0.y, af0.z, af0.w, af1.x, af1.y, af1.z, af1.w};
#pragma unroll
            for (int r = 0; r < 8; r++) {
                unsigned long long ap;
                asm("mov.b64 %0, {%1, %1};" : "=l"(ap) : "f"(av[r]));
                asm("fma.rn.f32x2 %0, %1, %2, %0;" : "+l"(acc[r][0]) : "l"(ap), "l"(bp0));
                asm("fma.rn.f32x2 %0, %1, %2, %0;" : "+l"(acc[r][1]) : "l"(ap), "l"(bp1));
                asm("fma.rn.f32x2 %0, %1, %2, %0;" : "+l"(acc[r][2]) : "l"(ap), "l"(bp2));
                asm("fma.rn.f32x2 %0, %1, %2, %0;" : "+l"(acc[r][3]) : "l"(ap), "l"(bp3));
            }
        }
        __syncthreads();
    }
    float bsv[8];
#pragma unroll
    for (int i = 0; i < 8; i++) bsv[i] = bias[n0 + tx * 8 + i];
#pragma unroll
    for (int r = 0; r < 8; r++) {
        int row = m0 + ty * 8 + r;
        float out[8];
#pragma unroll
        for (int c = 0; c < 4; c++) {
            float lo, hi;
            asm("mov.b64 {%0, %1}, %2;" : "=f"(lo), "=f"(hi) : "l"(acc[r][c]));
            out[2*c]   = lo + bsv[2*c];
            out[2*c+1] = hi + bsv[2*c+1];
        }
        *(float4*)&C[row * N + n0 + tx * 8]     = make_float4(out[0], out[1], out[2], out[3]);
        *(float4*)&C[row * N + n0 + tx * 8 + 4] = make_float4(out[4], out[5], out[6], out[7]);
    }
}

// ---------------- generic fp16 GEMM: C = A@B + bias, fp32 accum -------------
#define HLDA 72
#define HLDB 136
#define HSA (128 * HLDA)
#define HSB (64 * HLDB)
#define HSTG (HSA + HSB)
#define SMEM_HG (2 * HSTG * 2)

__device__ __forceinline__ void hg_load_stage(
    const __half* A, const __half* Bm, __half* sm, int stage,
    int m0, int n0, int kt, int K, int N, int tid)
{
    __half* sA = sm + stage * HSTG;
    __half* sB = sA + HSA;
#pragma unroll
    for (int i = 0; i < 4; i++) {
        int ch = tid + i * 256;
        int row = ch >> 3, c8 = ch & 7;
        uint32_t dst;
        asm("{ .reg .u64 t; cvta.to.shared.u64 t, %1; cvt.u32.u64 %0, t; }"
            : "=r"(dst) : "l"(sA + row * HLDA + c8 * 8));
        asm volatile("cp.async.cg.shared.global [%0], [%1], 16;"
                     :: "r"(dst), "l"(&A[(m0 + row) * K + kt * 64 + c8 * 8]));
    }
#pragma unroll
    for (int i = 0; i < 4; i++) {
        int ch = tid + i * 256;
        int row = ch >> 4, c8 = ch & 15;
        uint32_t dst;
        asm("{ .reg .u64 t; cvta.to.shared.u64 t, %1; cvt.u32.u64 %0, t; }"
            : "=r"(dst) : "l"(sB + row * HLDB + c8 * 8));
        asm volatile("cp.async.cg.shared.global [%0], [%1], 16;"
                     :: "r"(dst), "l"(&Bm[(kt * 64 + row) * N + n0 + c8 * 8]));
    }
    asm volatile("cp.async.commit_group;" ::: "memory");
}

__global__ __launch_bounds__(256) void k_hgemm_bias(
    const __half* __restrict__ A, const __half* __restrict__ Bm,
    const float* __restrict__ bias, float* __restrict__ C,
    int M, int N, int K)
{
    extern __shared__ __half smh[];
    const int tid = threadIdx.x;
    const int warp = tid >> 5;
    const int lane = tid & 31;
    const int wm = warp >> 1;
    const int wn = warp & 1;
    const int n0 = blockIdx.x * 128;
    const int m0 = blockIdx.y * 128;
    const int KT = K >> 6;

    float acc[2][8][4];
#pragma unroll
    for (int i = 0; i < 2; i++)
#pragma unroll
        for (int j = 0; j < 8; j++)
#pragma unroll
            for (int k = 0; k < 4; k++) acc[i][j][k] = 0.0f;

    hg_load_stage(A, Bm, smh, 0, m0, n0, 0, K, N, tid);

    const int a_row = wm * 32 + (lane & 15);
    const int a_col = (lane >> 4) * 8;
    const int b_row = (lane & 15);
    const int b_col = wn * 64 + (lane >> 4) * 8;

    for (int kt = 0; kt < KT; kt++) {
        if (kt + 1 < KT) {
            hg_load_stage(A, Bm, smh, (kt + 1) & 1, m0, n0, kt + 1, K, N, tid);
            asm volatile("cp.async.wait_group 1;" ::: "memory");
        } else {
            asm volatile("cp.async.wait_group 0;" ::: "memory");
        }
        __syncthreads();
        __half* sA = smh + (kt & 1) * HSTG;
        __half* sB = sA + HSA;
#pragma unroll
        for (int kk = 0; kk < 4; kk++) {
            unsigned af[2][4];
#pragma unroll
            for (int mt = 0; mt < 2; mt++) {
                unsigned saddr = (unsigned)__cvta_generic_to_shared(
                    &sA[(a_row + mt * 16) * HLDA + a_col + kk * 16]);
                asm volatile(
                    "ldmatrix.sync.aligned.m8n8.x4.shared.b16 {%0,%1,%2,%3}, [%4];"
                    : "=r"(af[mt][0]), "=r"(af[mt][1]), "=r"(af[mt][2]), "=r"(af[mt][3])
                    : "r"(saddr));
            }
            unsigned bfr[8][2];
#pragma unroll
            for (int nb = 0; nb < 4; nb++) {
                unsigned saddr = (unsigned)__cvta_generic_to_shared(
                    &sB[(b_row + kk * 16) * HLDB + b_col + nb * 16]);
                unsigned r0, r1, r2, r3;
                asm volatile(
                    "ldmatrix.sync.aligned.m8n8.x4.trans.shared.b16 {%0,%1,%2,%3}, [%4];"
                    : "=r"(r0), "=r"(r1), "=r"(r2), "=r"(r3)
                    : "r"(saddr));
                bfr[nb * 2][0] = r0;     bfr[nb * 2][1] = r1;
                bfr[nb * 2 + 1][0] = r2; bfr[nb * 2 + 1][1] = r3;
            }
#pragma unroll
            for (int mt = 0; mt < 2; mt++)
#pragma unroll
                for (int nt = 0; nt < 8; nt++) {
                    asm volatile(
                        "mma.sync.aligned.m16n8k16.row.col.f32.f16.f16.f32 "
                        "{%0,%1,%2,%3},{%4,%5,%6,%7},{%8,%9},{%0,%1,%2,%3};"
                        : "+f"(acc[mt][nt][0]), "+f"(acc[mt][nt][1]),
                          "+f"(acc[mt][nt][2]), "+f"(acc[mt][nt][3])
                        : "r"(af[mt][0]), "r"(af[mt][1]), "r"(af[mt][2]), "r"(af[mt][3]),
                          "r"(bfr[nt][0]), "r"(bfr[nt][1]));
                }
        }
        __syncthreads();
    }

#pragma unroll
    for (int mt = 0; mt < 2; mt++) {
        int row = m0 + wm * 32 + mt * 16 + (lane >> 2);
#pragma unroll
        for (int nt = 0; nt < 8; nt++) {
            int col = n0 + wn * 64 + nt * 8 + 2 * (lane & 3);
            float2 bb = *(const float2*)&bias[col];
            float2 v0 = make_float2(acc[mt][nt][0] + bb.x, acc[mt][nt][1] + bb.y);
            float2 v1 = make_float2(acc[mt][nt][2] + bb.x, acc[mt][nt][3] + bb.y);
            *(float2*)&C[row * N + col]       = v0;
            *(float2*)&C[(row + 8) * N + col] = v1;
        }
    }
}

// ---------------- K3: LSTM recurrence v4 — MUFU.TANH + prefetch dist 2 -----
// One warp per (batch, dir). Lane j owns h[j], c[j]; gate pairs (i,f),(g,o)
// packed f32x2; h broadcast via double-buffered smem; activations on the
// single-MUFU tanh.approx path (encoder only — error washed by softmax avg).
#define LSTM_STEP(XV, T)                                                      \
    do {                                                                      \
        float* buf = shh + ((T) & 1) * 64;                                    \
        buf[2 * j]     = h;                                                   \
        buf[2 * j + 1] = h;                                                   \
        __syncwarp();                                                         \
        unsigned long long aIF[4], aGO[4];                                    \
        asm("mov.b64 %0, {%1, %2};" : "=l"(aIF[0]) : "f"(XV[0]), "f"(XV[1])); \
        asm("mov.b64 %0, {%1, %2};" : "=l"(aGO[0]) : "f"(XV[2]), "f"(XV[3])); \
        aIF[1] = aIF[2] = aIF[3] = 0ULL;                                      \
        aGO[1] = aGO[2] = aGO[3] = 0ULL;                                      \
        int s_cur = dir ? (Ssz - 1 - (T)) : (T);                              \
        if ((T) + 2 < Ssz) {                                                  \
            int sp = dir ? (Ssz - 3 - (T)) : ((T) + 2);                       \
            const float* p = Xbase + sp * 256;                                \
            XV[0] = p[j];      XV[1] = p[32 + j];                             \
            XV[2] = p[64 + j]; XV[3] = p[96 + j];                             \
        }                                                                     \
        _Pragma("unroll")                                                     \
        for (int m = 0; m < 16; m++) {                                        \
            ulonglong2 hv = *(const ulonglong2*)&buf[4 * m];                  \
            int s0 = (m & 1) * 2;                                             \
            asm("fma.rn.f32x2 %0, %1, %2, %0;" : "+l"(aIF[s0])     : "l"(hv.x), "l"(uIF[2*m]));   \
            asm("fma.rn.f32x2 %0, %1, %2, %0;" : "+l"(aIF[s0 + 1]) : "l"(hv.y), "l"(uIF[2*m+1])); \
            asm("fma.rn.f32x2 %0, %1, %2, %0;" : "+l"(aGO[s0])     : "l"(hv.x), "l"(uGO[2*m]));   \
            asm("fma.rn.f32x2 %0, %1, %2, %0;" : "+l"(aGO[s0 + 1]) : "l"(hv.y), "l"(uGO[2*m+1])); \
        }                                                                     \
        asm("add.rn.f32x2 %0, %0, %1;" : "+l"(aIF[0]) : "l"(aIF[2]));         \
        asm("add.rn.f32x2 %0, %0, %1;" : "+l"(aIF[1]) : "l"(aIF[3]));         \
        asm("add.rn.f32x2 %0, %0, %1;" : "+l"(aIF[0]) : "l"(aIF[1]));         \
        asm("add.rn.f32x2 %0, %0, %1;" : "+l"(aGO[0]) : "l"(aGO[2]));         \
        asm("add.rn.f32x2 %0, %0, %1;" : "+l"(aGO[1]) : "l"(aGO[3]));         \
        asm("add.rn.f32x2 %0, %0, %1;" : "+l"(aGO[0]) : "l"(aGO[1]));         \
        float zi, zf, zg, zo;                                                 \
        asm("mov.b64 {%0, %1}, %2;" : "=f"(zi), "=f"(zf) : "l"(aIF[0]));      \
        asm("mov.b64 {%0, %1}, %2;" : "=f"(zg), "=f"(zo) : "l"(aGO[0]));      \
        c = siga(zf) * c + siga(zi) * tanha(zg);                              \
        h = siga(zo) * tanha(c);                                              \
        g_enc[(batch * Ssz + s_cur) * 64 + dir * 32 + j] = h;                 \
    } while (0)

__global__ __launch_bounds__(32) void k_lstm_warp(const float* __restrict__ Uf,
                                                  const float* __restrict__ Ub) {
    __shared__ __align__(16) float shh[128];   // 2 buffers x 64 floats
    int blk = blockIdx.x;
    int batch = blk >> 1;
    int dir = blk & 1;
    const float* U = dir ? Ub : Uf;
    int j = threadIdx.x;

    unsigned long long uIF[32], uGO[32];  // packed (Ui,Uf), (Ug,Uo) columns
#pragma unroll
    for (int k = 0; k < 32; k++) {
        float a = U[k * 128 + j];
        float b = U[k * 128 + 32 + j];
        float g = U[k * 128 + 64 + j];
        float o = U[k * 128 + 96 + j];
        asm("mov.b64 %0, {%1, %2};" : "=l"(uIF[k]) : "f"(a), "f"(b));
        asm("mov.b64 %0, {%1, %2};" : "=l"(uGO[k]) : "f"(g), "f"(o));
    }

    float h = 0.0f, c = 0.0f;
    const float* Xbase = g_Xc + batch * Ssz * 256 + dir * 128;

    // prefetch steps 0 and 1 (distance-2 pipeline)
    float xA[4], xB[4];
    {
        int s0i = dir ? (Ssz - 1) : 0;
        const float* p = Xbase + s0i * 256;
        xA[0] = p[j]; xA[1] = p[32 + j]; xA[2] = p[64 + j]; xA[3] = p[96 + j];
        int s1i = dir ? (Ssz - 2) : 1;
        const float* q = Xbase + s1i * 256;
        xB[0] = q[j]; xB[1] = q[32 + j]; xB[2] = q[64 + j]; xB[3] = q[96 + j];
    }

    for (int t = 0; t < Ssz; t += 2) {
        LSTM_STEP(xA, t);
        LSTM_STEP(xB, t + 1);
    }
    g_hidden[batch * 64 + dir * 32 + j] = h;
}

// ---------------- K4: attention --------------------------------------------
__global__ void k_q(const float* __restrict__ W1, const float* __restrict__ b1) {
    __shared__ float hh[64];
    int b = blockIdx.x, t = threadIdx.x;
    if (t < 64) hh[t] = g_hidden[b * 64 + t];
    __syncthreads();
    float acc = b1[t];
#pragma unroll
    for (int k = 0; k < 64; k++) acc += hh[k] * W1[k * 128 + t];
    g_q[b * 128 + t] = acc;
}

__global__ void k_score(const float* __restrict__ Vw, const float* __restrict__ Vb) {
    int warp = threadIdx.x >> 5;
    int lane = threadIdx.x & 31;
    int row = blockIdx.x * 8 + warp;
    int b = row >> 9;
    const float* Prow = g_P + row * 128;
    const float* qrow = g_q + b * 128;
    float sum = 0.0f;
#pragma unroll
    for (int i = 0; i < 4; i++) {
        int d = i * 32 + lane;
        sum += tanhfast(Prow[d] + qrow[d]) * Vw[d];
    }
#pragma unroll
    for (int o = 16; o > 0; o >>= 1) sum += __shfl_xor_sync(0xffffffffu, sum, o);
    if (lane == 0) g_scores[row] = sum + Vb[0];
}

__global__ __launch_bounds__(256) void k_attn() {
    __shared__ float sw[512];
    __shared__ float sbuf[256];
    int b = blockIdx.x, tid = threadIdx.x;
    float s0 = g_scores[b * 512 + tid];
    float s1 = g_scores[b * 512 + 256 + tid];
    sbuf[tid] = fmaxf(s0, s1);
    __syncthreads();
    for (int o = 128; o > 0; o >>= 1) {
        if (tid < o) sbuf[tid] = fmaxf(sbuf[tid], sbuf[tid + o]);
        __syncthreads();
    }
    float mx = sbuf[0];
    __syncthreads();
    float w0 = __expf(s0 - mx), w1 = __expf(s1 - mx);
    sw[tid] = w0; sw[tid + 256] = w1;
    sbuf[tid] = w0 + w1;
    __syncthreads();
    for (int o = 128; o > 0; o >>= 1) {
        if (tid < o) sbuf[tid] += sbuf[tid + o];
        __syncthreads();
    }
    float inv = 1.0f / sbuf[0];
    __syncthreads();
    int k = tid & 63, chunk = tid >> 6;
    float partial = 0.0f;
    for (int s = chunk * 128; s < chunk * 128 + 128; s++)
        partial += sw[s] * g_enc[(b * 512 + s) * 64 + k];
    sbuf[tid] = partial;
    __syncthreads();
    if (tid < 64)
        g_ctx[b * 64 + tid] =
            (sbuf[tid] + sbuf[tid + 64] + sbuf[tid + 128] + sbuf[tid + 192]) * inv;
}

// ---------------- K5: decoder ------------------------------------------------
__global__ void k_buildx(const int* __restrict__ tgt, const float* __restrict__ temb) {
    int row = blockIdx.x;
    int t = threadIdx.x;
    float v;
    if (t < 64) v = g_ctx[(row >> 7) * 64 + t];
    else        v = temb[tgt[row] * 256 + (t - 64)];
    g_Xh[row * 320 + t] = __float2half(v);
}

__global__ void k_gateA() {
    int idx = blockIdx.x * 256 + threadIdx.x;
    int row = idx >> 7, j = idx & 127;
    const float* z = g_Z + row * 512;
    float c = sigf(z[j]) * tanhfast(z[256 + j]);        // i, g (f is dead)
    float h = sigf(z[384 + j]) * tanhfast(c);           // o
    g_Ah[idx] = __float2half(h);
}

// ---------------- K6: vocab projection, fp16 mma.sync (one-shot K=128) ------
#define LDT 136
#define SMEM_VOC (2 * 128 * LDT * 2)   // sA + sB fp16

__global__ __launch_bounds__(256, 2) void k_vocab_f16(const float* __restrict__ bias,
                                                      float* __restrict__ C) {
    extern __shared__ __half smh[];
    __half* sA = smh;                  // 128 x LDT
    __half* sB = smh + 128 * LDT;      // 128 x LDT
    const int tid = threadIdx.x;
    const int warp = tid >> 5;
    const int lane = tid & 31;
    const int wm = warp >> 1;
    const int wn = warp & 1;
    const int n0 = blockIdx.x * 128;
    const int m0 = blockIdx.y * 128;

#pragma unroll
    for (int i = 0; i < 8; i++) {
        int ch = tid + i * 256;
        int row = ch >> 4, c8 = ch & 15;
        uint32_t dst;
        asm("{ .reg .u64 t; cvta.to.shared.u64 t, %1; cvt.u32.u64 %0, t; }"
            : "=r"(dst) : "l"(sA + row * LDT + c8 * 8));
        asm volatile("cp.async.cg.shared.global [%0], [%1], 16;"
                     :: "r"(dst), "l"(&g_Ah[(m0 + row) * GKH + c8 * 8]));
    }
#pragma unroll
    for (int i = 0; i < 8; i++) {
        int ch = tid + i * 256;
        int row = ch >> 4, c8 = ch & 15;
        uint32_t dst;
        asm("{ .reg .u64 t; cvta.to.shared.u64 t, %1; cvt.u32.u64 %0, t; }"
            : "=r"(dst) : "l"(sB + row * LDT + c8 * 8));
        asm volatile("cp.async.cg.shared.global [%0], [%1], 16;"
                     :: "r"(dst), "l"(&g_Bh[row * GN + n0 + c8 * 8]));
    }
    asm volatile("cp.async.commit_group;" ::: "memory");
    asm volatile("cp.async.wait_group 0;" ::: "memory");
    __syncthreads();

    float acc[2][8][4];
#pragma unroll
    for (int i = 0; i < 2; i++)
#pragma unroll
        for (int j = 0; j < 8; j++)
#pragma unroll
            for (int k = 0; k < 4; k++) acc[i][j][k] = 0.0f;

    const int a_row = wm * 32 + (lane & 15);
    const int a_col = (lane >> 4) * 8;
    const int b_row = (lane & 15);
    const int b_col = wn * 64 + (lane >> 4) * 8;

#pragma unroll
    for (int kk = 0; kk < 8; kk++) {
        unsigned af[2][4];
#pragma unroll
        for (int mt = 0; mt < 2; mt++) {
            unsigned saddr = (unsigned)__cvta_generic_to_shared(
                &sA[(a_row + mt * 16) * LDT + a_col + kk * 16]);
            asm volatile(
                "ldmatrix.sync.aligned.m8n8.x4.shared.b16 {%0,%1,%2,%3}, [%4];"
                : "=r"(af[mt][0]), "=r"(af[mt][1]), "=r"(af[mt][2]), "=r"(af[mt][3])
                : "r"(saddr));
        }
        unsigned bfr[8][2];
#pragma unroll
        for (int nb = 0; nb < 4; nb++) {
            unsigned saddr = (unsigned)__cvta_generic_to_shared(
                &sB[(b_row + kk * 16) * LDT + b_col + nb * 16]);
            unsigned r0, r1, r2, r3;
            asm volatile(
                "ldmatrix.sync.aligned.m8n8.x4.trans.shared.b16 {%0,%1,%2,%3}, [%4];"
                : "=r"(r0), "=r"(r1), "=r"(r2), "=r"(r3)
                : "r"(saddr));
            bfr[nb * 2][0] = r0;     bfr[nb * 2][1] = r1;
            bfr[nb * 2 + 1][0] = r2; bfr[nb * 2 + 1][1] = r3;
        }
#pragma unroll
        for (int mt = 0; mt < 2; mt++)
#pragma unroll
            for (int nt = 0; nt < 8; nt++) {
                asm volatile(
                    "mma.sync.aligned.m16n8k16.row.col.f32.f16.f16.f32 "
                    "{%0,%1,%2,%3},{%4,%5,%6,%7},{%8,%9},{%0,%1,%2,%3};"
                    : "+f"(acc[mt][nt][0]), "+f"(acc[mt][nt][1]),
                      "+f"(acc[mt][nt][2]), "+f"(acc[mt][nt][3])
                    : "r"(af[mt][0]), "r"(af[mt][1]), "r"(af[mt][2]), "r"(af[mt][3]),
                      "r"(bfr[nt][0]), "r"(bfr[nt][1]));
            }
    }

#pragma unroll
    for (int mt = 0; mt < 2; mt++) {
        int row = m0 + wm * 32 + mt * 16 + (lane >> 2);
#pragma unroll
        for (int nt = 0; nt < 8; nt++) {
            int col = n0 + wn * 64 + nt * 8 + 2 * (lane & 3);
            float2 bb = *(const float2*)&bias[col];
            float2 v0 = make_float2(acc[mt][nt][0] + bb.x, acc[mt][nt][1] + bb.y);
            float2 v1 = make_float2(acc[mt][nt][2] + bb.x, acc[mt][nt][3] + bb.y);
            *(float2*)&C[row * GN + col]       = v0;
            *(float2*)&C[(row + 8) * GN + col] = v1;
        }
    }
}

// ---------------- host launcher ---------------------------------------------
extern "C" void kernel_launch(void* const* d_in, const int* in_sizes, int n_in,
                              void* d_out, int out_size) {
    const int*   source  = (const int*)d_in[0];
    const int*   target  = (const int*)d_in[1];
    const float* src_emb = (const float*)d_in[2];
    const float* tgt_emb = (const float*)d_in[3];
    const float* Wf = (const float*)d_in[4];
    const float* Uf = (const float*)d_in[5];
    const float* bf = (const float*)d_in[6];
    const float* Wb = (const float*)d_in[7];
    const float* Ub = (const float*)d_in[8];
    const float* bb = (const float*)d_in[9];
    const float* W1 = (const float*)d_in[10];
    const float* b1 = (const float*)d_in[11];
    const float* W2 = (const float*)d_in[12];
    const float* b2 = (const float*)d_in[13];
    const float* Vw = (const float*)d_in[14];
    const float* Vb = (const float*)d_in[15];
    const float* Wd = (const float*)d_in[16];
    const float* bd = (const float*)d_in[17];
    const float* Wfc = (const float*)d_in[18];
    const float* bfc = (const float*)d_in[19];
    float* out = (float*)d_out;

    __half *p_srch, *p_Wcath, *p_Wdh, *p_Xh;
    float *p_Xc, *p_bcat, *p_enc, *p_P, *p_Z;
    cudaGetSymbolAddress((void**)&p_srch,  g_srch);
    cudaGetSymbolAddress((void**)&p_Wcath, g_Wcath);
    cudaGetSymbolAddress((void**)&p_Wdh,   g_Wdh);
    cudaGetSymbolAddress((void**)&p_Xh,    g_Xh);
    cudaGetSymbolAddress((void**)&p_Xc,    g_Xc);
    cudaGetSymbolAddress((void**)&p_bcat,  g_bcat);
    cudaGetSymbolAddress((void**)&p_enc,   g_enc);
    cudaGetSymbolAddress((void**)&p_P,     g_P);
    cudaGetSymbolAddress((void**)&p_Z,     g_Z);

    cudaFuncSetAttribute(k_vocab_f16,
                         cudaFuncAttributeMaxDynamicSharedMemorySize, SMEM_VOC);
    cudaFuncSetAttribute(k_hgemm_bias,
                         cudaFuncAttributeMaxDynamicSharedMemorySize, SMEM_HG);

    // critical path first (launch #4 = k_lstm_warp, for ncu's sampled slot)
    k_cat<<<256, 256>>>(Wf, bf, Wb, bb);
    k_embed<<<Bsz * Ssz, 256>>>(source, src_emb);
    k_hgemm_bias<<<dim3(2, 64), 256, SMEM_HG>>>(p_srch, p_Wcath, p_bcat, p_Xc, 8192, 256, 256);
    k_lstm_warp<<<32, 32>>>(Uf, Ub);
    // independent prep (off critical path)
    k_convB16<<<dim3(GN / 256, GKH), 256>>>(Wfc);
    k_convWd<<<640, 256>>>(Wd);
    // attention
    k_q<<<16, 128>>>(W1, b1);
    k_sgemm_bias<<<dim3(1, 64), 256>>>(p_enc, W2, b2, p_P, 8192, 128, 64);
    k_score<<<1024, 256>>>(Vw, Vb);
    k_attn<<<16, 256>>>();
    // decoder
    k_buildx<<<2048, 320>>>(target, tgt_emb);
    k_hgemm_bias<<<dim3(4, 16), 256, SMEM_HG>>>(p_Xh, p_Wdh, bd, p_Z, 2048, 512, 320);
    k_gateA<<<1024, 256>>>();
    // vocab projection
    k_vocab_f16<<<dim3(GN / 128, GM / 128), 256, SMEM_VOC>>>(bfc, out);
}